// round 11
// baseline (speedup 1.0000x reference)
#include <cuda_runtime.h>
#include <math.h>
#include <stdint.h>

// ---------------- problem constants ----------------
#define T_      2048
#define D_      2048
#define DL_     1024
#define E_      64
#define I_      768
#define SI_     4096
#define TOPK    6
#define NGROUP  8
#define GSIZE   8
#define TOPKG   4
#define CAP_    384
#define RSCALE  2.5f

// ---------------- bf16 hi/lo plane arenas ----------------
#define X_SZ   (T_ * D_)
#define FC1_SZ (DL_ * D_)
#define FC2_SZ (D_ * DL_)
#define W1_SZ  ((size_t)E_ * I_ * DL_)
#define W2_SZ  ((size_t)E_ * DL_ * I_)
#define SW1_SZ (SI_ * D_)
#define SW2_SZ (D_ * SI_)
#define XL_SZ  (T_ * DL_)
#define H_SZ   ((size_t)E_ * CAP_ * I_)
#define S1_SZ  ((size_t)T_ * SI_)
#define R_SZ   (T_ * DL_)

#define X_OFF   ((size_t)0)
#define FC1_OFF (X_OFF + X_SZ)
#define FC2_OFF (FC1_OFF + FC1_SZ)
#define W1_OFF  (FC2_OFF + FC2_SZ)
#define W2_OFF  (W1_OFF + W1_SZ)
#define SW1_OFF (W2_OFF + W2_SZ)
#define SW2_OFF (SW1_OFF + SW1_SZ)
#define XL_OFF  (SW2_OFF + SW2_SZ)
#define H_OFF   (XL_OFF + XL_SZ)
#define S1_OFF  (H_OFF + H_SZ)
#define R_OFF   (S1_OFF + S1_SZ)
#define ARENA_SZ (R_OFF + R_SZ)

__device__ uint16_t g_hiA[ARENA_SZ];
__device__ uint16_t g_loA[ARENA_SZ];

__device__ float g_scores[T_ * E_];
__device__ float g_eout[(size_t)E_ * CAP_ * DL_];
__device__ int   g_tidx[T_ * TOPK];
__device__ float g_tw[T_ * TOPK];
__device__ int   g_counts[E_];
__device__ int   g_toklist[E_ * CAP_];
__device__ int   g_slot[T_ * TOPK];

// =====================================================================
// helpers
// =====================================================================
__device__ __forceinline__ uint32_t smem_u32(const void* p) {
    uint32_t a;
    asm("{ .reg .u64 t; cvta.to.shared.u64 t, %1; cvt.u32.u64 %0, t; }" : "=r"(a) : "l"(p));
    return a;
}
__device__ __forceinline__ uint32_t pack_bf2(float lo, float hi) {
    uint32_t r;
    asm("cvt.rn.bf16x2.f32 %0, %1, %2;" : "=r"(r) : "f"(hi), "f"(lo));
    return r;
}
__device__ __forceinline__ void split4(float4 v, uint2& h, uint2& l) {
    h.x = pack_bf2(v.x, v.y); h.y = pack_bf2(v.z, v.w);
    float f0 = __uint_as_float(h.x << 16), f1 = __uint_as_float(h.x & 0xffff0000u);
    float f2 = __uint_as_float(h.y << 16), f3 = __uint_as_float(h.y & 0xffff0000u);
    l.x = pack_bf2(v.x - f0, v.y - f1); l.y = pack_bf2(v.z - f2, v.w - f3);
}
__device__ __forceinline__ void ldm_x4(uint32_t* r, uint32_t a) {
    asm volatile("ldmatrix.sync.aligned.m8n8.x4.shared.b16 {%0,%1,%2,%3}, [%4];"
                 : "=r"(r[0]), "=r"(r[1]), "=r"(r[2]), "=r"(r[3]) : "r"(a));
}
__device__ __forceinline__ void mma_bf16(float* d, const uint32_t* a, uint32_t b0, uint32_t b1) {
    asm volatile(
        "mma.sync.aligned.m16n8k16.row.col.f32.bf16.bf16.f32 "
        "{%0,%1,%2,%3},{%4,%5,%6,%7},{%8,%9},{%0,%1,%2,%3};"
        : "+f"(d[0]), "+f"(d[1]), "+f"(d[2]), "+f"(d[3])
        : "r"(a[0]), "r"(a[1]), "r"(a[2]), "r"(a[3]), "r"(b0), "r"(b1));
}
__device__ __forceinline__ void cp16(uint32_t dst, const void* src, int srcsize) {
    asm volatile("cp.async.cg.shared.global [%0], [%1], 16, %2;"
                 :: "r"(dst), "l"(src), "r"(srcsize) : "memory");
}
#define CP_COMMIT() asm volatile("cp.async.commit_group;" ::: "memory")
#define CP_WAIT1()  asm volatile("cp.async.wait_group 1;" ::: "memory")
#define CP_WAIT0()  asm volatile("cp.async.wait_group 0;" ::: "memory")

// smem stage: 4 bf16 tiles of 128 rows x 32 cols, row stride 80B
#define RSTRIDE 80
#define AHI_OFF 0
#define ALO_OFF 10240
#define BHI_OFF 20480
#define BLO_OFF 30720
#define STAGE_B 40960
#define SMEM_BYTES (2 * STAGE_B)

// =====================================================================
// convert fp32 -> bf16 hi/lo planes
// =====================================================================
__global__ void cvt_kernel(const float4* __restrict__ src,
                           uint2* __restrict__ hi, uint2* __restrict__ lo, int n4)
{
    int i = blockIdx.x * blockDim.x + threadIdx.x;
    if (i >= n4) return;
    float4 v = src[i];
    uint2 h, l;
    split4(v, h, l);
    hi[i] = h; lo[i] = l;
}

// =====================================================================
// split-bf16 HMMA GEMM on pre-split planes, cp.async G2S, occ 2.
// A:[M,K], B:[N,K] hi/lo bf16 planes. 128x128x32 tiles, 256 threads,
// 8 warps (4Mx2N), warp tile 32x64, mma.m16n8k16, fp32 accum, 3-MMA.
// OMODE: 0 fp32 out, 1 fp32 accumulate, 2 bf16 hi/lo plane out.
// =====================================================================
template <int EPI, int OMODE>
__global__ __launch_bounds__(256, 2)
void hmma_gemm(const uint16_t* __restrict__ Ah, const uint16_t* __restrict__ Al,
               const uint16_t* __restrict__ Bh, const uint16_t* __restrict__ Bl,
               float* __restrict__ Cf,
               uint16_t* __restrict__ Ch, uint16_t* __restrict__ Cl,
               int M, int N, int K,
               long sAz, long sBz, long sCz,
               const int* __restrict__ gatherB, long sGz,
               const int* __restrict__ counts)
{
    extern __shared__ char sm[];
    const int z = blockIdx.z;
    Ah += (size_t)z * sAz; Al += (size_t)z * sAz;
    Bh += (size_t)z * sBz; Bl += (size_t)z * sBz;
    if (OMODE == 2) { Ch += (size_t)z * sCz; Cl += (size_t)z * sCz; }
    else            { Cf += (size_t)z * sCz; }
    const int* g = gatherB ? (gatherB + (size_t)z * sGz) : nullptr;

    int rowLimit = M;
    if (counts) { int c = counts[z]; rowLimit = (c < M) ? c : M; }
    const int m0 = blockIdx.y * 128;
    const int n0 = blockIdx.x * 128;
    if (m0 >= rowLimit) return;

    const uint32_t sbase = smem_u32(sm);
    const int tid  = threadIdx.x;
    const int lane = tid & 31;
    const int wid  = tid >> 5;
    const int warp_m = wid & 3;
    const int warp_n = wid >> 2;

    // ---- cp.async loader: 2 threads per row, 2x16B per plane each ----
    const int lrow = tid >> 1;
    const int lhalf = (tid & 1) * 32;          // byte offset within 64B row chunk
    const char *pAh, *pAl;
    int aSz;
    {
        int ar = m0 + lrow;
        if (ar < rowLimit) {
            int src = g ? g[ar] : ar;
            pAh = (const char*)(Ah + (size_t)src * K) + lhalf;
            pAl = (const char*)(Al + (size_t)src * K) + lhalf;
            aSz = 16;
        } else { pAh = (const char*)Ah; pAl = (const char*)Al; aSz = 0; }
    }
    const char* pBh = (const char*)(Bh + (size_t)(n0 + lrow) * K) + lhalf;
    const char* pBl = (const char*)(Bl + (size_t)(n0 + lrow) * K) + lhalf;

    const uint32_t sdst = lrow * RSTRIDE + lhalf;
    const int KT = K >> 5;

    float acc[2][8][4];
#pragma unroll
    for (int im = 0; im < 2; im++)
#pragma unroll
        for (int in = 0; in < 8; in++)
#pragma unroll
            for (int q = 0; q < 4; q++) acc[im][in][q] = 0.f;

    // prologue: issue stage 0
    {
        uint32_t d = sbase + sdst;
        cp16(d + AHI_OFF, pAh, aSz);      cp16(d + AHI_OFF + 16, pAh + 16, aSz);
        cp16(d + ALO_OFF, pAl, aSz);      cp16(d + ALO_OFF + 16, pAl + 16, aSz);
        cp16(d + BHI_OFF, pBh, 16);       cp16(d + BHI_OFF + 16, pBh + 16, 16);
        cp16(d + BLO_OFF, pBl, 16);       cp16(d + BLO_OFF + 16, pBl + 16, 16);
        CP_COMMIT();
    }

    // B ldmatrix address components
    const int bt   = lane >> 3;
    const int brow = lane & 7;
    const uint32_t bn_off = (uint32_t)((warp_n * 64 + ((bt >> 1) * 8) + brow) * RSTRIDE
                                       + (bt & 1) * 16);

    for (int kt = 0; kt < KT; ++kt) {
        const int cur = kt & 1;
        const bool more = (kt + 1 < KT);
        if (more) {
            uint32_t d = sbase + (cur ? 0 : STAGE_B) + sdst;
            int off = (kt + 1) * 64;
            cp16(d + AHI_OFF, pAh + off, aSz);  cp16(d + AHI_OFF + 16, pAh + off + 16, aSz);
            cp16(d + ALO_OFF, pAl + off, aSz);  cp16(d + ALO_OFF + 16, pAl + off + 16, aSz);
            cp16(d + BHI_OFF, pBh + off, 16);   cp16(d + BHI_OFF + 16, pBh + off + 16, 16);
            cp16(d + BLO_OFF, pBl + off, 16);   cp16(d + BLO_OFF + 16, pBl + off + 16, 16);
            CP_COMMIT();
            CP_WAIT1();
        } else {
            CP_WAIT0();
        }
        __syncthreads();

        const uint32_t sb = sbase + (cur ? STAGE_B : 0);
#pragma unroll
        for (int k16 = 0; k16 < 2; k16++) {
            uint32_t ah[2][4], al[2][4];
#pragma unroll
            for (int im = 0; im < 2; im++) {
                uint32_t row = warp_m * 32 + im * 16 + (lane & 15);
                uint32_t addr = sb + row * RSTRIDE + k16 * 32 + (lane >> 4) * 16;
                ldm_x4(ah[im], addr + AHI_OFF);
                ldm_x4(al[im], addr + ALO_OFF);
            }
#pragma unroll
            for (int gp = 0; gp < 4; gp++) {
                uint32_t addr = sb + bn_off + gp * 16 * RSTRIDE + k16 * 32;
                uint32_t bh4[4], bl4[4];
                ldm_x4(bh4, addr + BHI_OFF);
                ldm_x4(bl4, addr + BLO_OFF);
#pragma unroll
                for (int j = 0; j < 2; j++) {
                    const int in = 2 * gp + j;
#pragma unroll
                    for (int im = 0; im < 2; im++) {
                        mma_bf16(acc[im][in], ah[im], bh4[2 * j], bh4[2 * j + 1]);
                        mma_bf16(acc[im][in], ah[im], bl4[2 * j], bl4[2 * j + 1]);
                        mma_bf16(acc[im][in], al[im], bh4[2 * j], bh4[2 * j + 1]);
                    }
                }
            }
        }
        __syncthreads();   // protect stage cur before re-issue at kt+2
    }

    // ---- epilogue ----
#pragma unroll
    for (int im = 0; im < 2; im++) {
        int row0 = m0 + warp_m * 32 + im * 16 + (lane >> 2);
#pragma unroll
        for (int half = 0; half < 2; half++) {
            int r = row0 + half * 8;
#pragma unroll
            for (int in = 0; in < 8; in++) {
                int col = n0 + warp_n * 64 + in * 8 + (lane & 3) * 2;
                float x0 = acc[im][in][half * 2 + 0];
                float x1 = acc[im][in][half * 2 + 1];
                if (EPI == 2) {
                    float r0 = fmaxf(x0, 0.f), r1 = fmaxf(x1, 0.f);
                    x0 = r0 * r0; x1 = r1 * r1;
                }
                if (OMODE == 2) {
                    uint32_t hp = pack_bf2(x0, x1);
                    float f0 = __uint_as_float(hp << 16);
                    float f1 = __uint_as_float(hp & 0xffff0000u);
                    uint32_t lp = pack_bf2(x0 - f0, x1 - f1);
                    *(uint32_t*)(Ch + (size_t)r * N + col) = hp;
                    *(uint32_t*)(Cl + (size_t)r * N + col) = lp;
                } else {
                    float* crow = Cf + (size_t)r * N;
                    if (OMODE == 1) {
                        float2 old = *(const float2*)(crow + col);
                        x0 += old.x; x1 += old.y;
                    }
                    *(float2*)(crow + col) = make_float2(x0, x1);
                }
            }
        }
    }
}

// =====================================================================
// SIMT GEMM for the gate (N=64 only)
// =====================================================================
template <int EPI>
__global__ __launch_bounds__(256, 2)
void gemm_bt(const float* __restrict__ A, const float* __restrict__ B,
             float* __restrict__ C, int M, int N, int K)
{
    const int m0 = blockIdx.y * 128;
    const int n0 = blockIdx.x * 128;
    __shared__ float As[2][8][132];
    __shared__ float Bs[2][8][132];
    const int tid = threadIdx.x;
    const int tx = tid & 15, ty = tid >> 4;
    const int lr = tid >> 1, lk = (tid & 1) * 4;
    float acc[8][8];
#pragma unroll
    for (int i = 0; i < 8; i++)
#pragma unroll
        for (int j = 0; j < 8; j++) acc[i][j] = 0.f;
    const int KT = K >> 3;
    const float* Arow = (m0 + lr < M) ? A + (size_t)(m0 + lr) * K : nullptr;
    const float* Brow = (n0 + lr < N) ? B + (size_t)(n0 + lr) * K : nullptr;
    {
        float4 va = Arow ? *(const float4*)(Arow + lk) : make_float4(0, 0, 0, 0);
        float4 vb = Brow ? *(const float4*)(Brow + lk) : make_float4(0, 0, 0, 0);
        As[0][lk][lr] = va.x; As[0][lk + 1][lr] = va.y; As[0][lk + 2][lr] = va.z; As[0][lk + 3][lr] = va.w;
        Bs[0][lk][lr] = vb.x; Bs[0][lk + 1][lr] = vb.y; Bs[0][lk + 2][lr] = vb.z; Bs[0][lk + 3][lr] = vb.w;
    }
    __syncthreads();
    for (int kt = 0; kt < KT; ++kt) {
        const int cur = kt & 1, nxt = cur ^ 1;
        float4 va = make_float4(0, 0, 0, 0), vb = make_float4(0, 0, 0, 0);
        const bool more = (kt + 1 < KT);
        if (more) {
            int k0 = (kt + 1) << 3;
            if (Arow) va = *(const float4*)(Arow + k0 + lk);
            if (Brow) vb = *(const float4*)(Brow + k0 + lk);
        }
#pragma unroll
        for (int k = 0; k < 8; k++) {
            float4 a0 = *(const float4*)&As[cur][k][ty * 4];
            float4 a1 = *(const float4*)&As[cur][k][64 + ty * 4];
            float4 b0 = *(const float4*)&Bs[cur][k][tx * 4];
            float4 b1 = *(const float4*)&Bs[cur][k][64 + tx * 4];
            float a[8] = {a0.x, a0.y, a0.z, a0.w, a1.x, a1.y, a1.z, a1.w};
            float b[8] = {b0.x, b0.y, b0.z, b0.w, b1.x, b1.y, b1.z, b1.w};
#pragma unroll
            for (int i = 0; i < 8; i++)
#pragma unroll
                for (int j = 0; j < 8; j++) acc[i][j] += a[i] * b[j];
        }
        if (more) {
            As[nxt][lk][lr] = va.x; As[nxt][lk + 1][lr] = va.y; As[nxt][lk + 2][lr] = va.z; As[nxt][lk + 3][lr] = va.w;
            Bs[nxt][lk][lr] = vb.x; Bs[nxt][lk + 1][lr] = vb.y; Bs[nxt][lk + 2][lr] = vb.z; Bs[nxt][lk + 3][lr] = vb.w;
        }
        __syncthreads();
    }
#pragma unroll
    for (int ri = 0; ri < 2; ri++)
#pragma unroll
        for (int i = 0; i < 4; i++) {
            int r = m0 + ri * 64 + ty * 4 + i;
            if (r >= M) continue;
            float* Crow = C + (size_t)r * N;
#pragma unroll
            for (int ci = 0; ci < 2; ci++) {
                int c = n0 + ci * 64 + tx * 4;
                if (c >= N) continue;
                float v[4];
#pragma unroll
                for (int j = 0; j < 4; j++) {
                    float x = acc[ri * 4 + i][ci * 4 + j];
                    if (EPI == 1) x = 1.f / (1.f + expf(-x));
                    v[j] = x;
                }
                *(float4*)(Crow + c) = make_float4(v[0], v[1], v[2], v[3]);
            }
        }
}

// ================================================================
// routing / dispatch / combine
// ================================================================
__global__ void routing_kernel(const float* __restrict__ scores,
                               const float* __restrict__ bias)
{
    int t = blockIdx.x * blockDim.x + threadIdx.x;
    if (t >= T_) return;
    float s[E_], m[E_];
    const float* sr = scores + t * E_;
#pragma unroll
    for (int e = 0; e < E_; e++) s[e] = sr[e];
    float gs[NGROUP];
    for (int gi = 0; gi < NGROUP; gi++) {
        float m1 = -1e30f, m2 = -1e30f;
        for (int j = 0; j < GSIZE; j++) {
            float v = s[gi * GSIZE + j] + bias[gi * GSIZE + j];
            if (v > m1) { m2 = m1; m1 = v; } else if (v > m2) m2 = v;
        }
        gs[gi] = m1 + m2;
    }
    bool gsel[NGROUP];
    for (int gi = 0; gi < NGROUP; gi++) gsel[gi] = false;
    for (int it = 0; it < TOPKG; it++) {
        float best = -1e30f; int bi = 0;
        for (int gi = 0; gi < NGROUP; gi++)
            if (!gsel[gi] && gs[gi] > best) { best = gs[gi]; bi = gi; }
        gsel[bi] = true;
    }
    for (int e = 0; e < E_; e++)
        m[e] = gsel[e / GSIZE] ? (s[e] + bias[e]) : 0.0f;
    float wsum = 0.f;
    int sel_e[TOPK]; float sel_w[TOPK];
    for (int k = 0; k < TOPK; k++) {
        float best = -1e30f; int bi = 0;
        for (int e = 0; e < E_; e++)
            if (m[e] > best) { best = m[e]; bi = e; }
        m[bi] = -1e30f;
        sel_e[k] = bi; sel_w[k] = s[bi]; wsum += s[bi];
    }
    float inv = RSCALE / (wsum + 1e-20f);
    for (int k = 0; k < TOPK; k++) {
        g_tidx[t * TOPK + k] = sel_e[k];
        g_tw[t * TOPK + k] = sel_w[k] * inv;
    }
}

__global__ void zero_counts_kernel()
{
    if (threadIdx.x < E_) g_counts[threadIdx.x] = 0;
}

__global__ void dispatch_kernel()
{
    int i = blockIdx.x * blockDim.x + threadIdx.x;
    if (i >= T_ * TOPK) return;
    int e = g_tidx[i];
    int p = atomicAdd(&g_counts[e], 1);
    if (p < CAP_) {
        int sl = e * CAP_ + p;
        g_toklist[sl] = i / TOPK;
        g_slot[i] = sl;
    } else g_slot[i] = -1;
}

__global__ void combine_kernel(uint16_t* __restrict__ rh, uint16_t* __restrict__ rl)
{
    const int nd4 = DL_ / 4;
    int idx = blockIdx.x * blockDim.x + threadIdx.x;
    if (idx >= T_ * nd4) return;
    int t = idx / nd4, d4 = idx % nd4;
    float4 acc = make_float4(0, 0, 0, 0);
#pragma unroll
    for (int k = 0; k < TOPK; k++) {
        int s = g_slot[t * TOPK + k];
        if (s >= 0) {
            float w = g_tw[t * TOPK + k];
            float4 v = *(const float4*)(g_eout + (size_t)s * DL_ + d4 * 4);
            acc.x += w * v.x; acc.y += w * v.y;
            acc.z += w * v.z; acc.w += w * v.w;
        }
    }
    uint2 h, l;
    split4(acc, h, l);
    *(uint2*)(rh + (size_t)t * DL_ + d4 * 4) = h;
    *(uint2*)(rl + (size_t)t * DL_ + d4 * 4) = l;
}

// ================================================================
extern "C" void kernel_launch(void* const* d_in, const int* in_sizes, int n_in,
                              void* d_out, int out_size)
{
    (void)in_sizes; (void)n_in; (void)out_size;
    const float* x      = (const float*)d_in[0];
    const float* gate_w = (const float*)d_in[1];
    const float* gate_b = (const float*)d_in[2];
    const float* fc1_w  = (const float*)d_in[3];
    const float* fc2_w  = (const float*)d_in[4];
    const float* w1     = (const float*)d_in[5];
    const float* w2     = (const float*)d_in[6];
    const float* sw1    = (const float*)d_in[7];
    const float* sw2    = (const float*)d_in[8];
    float* out = (float*)d_out;

    uint16_t *hi, *lo;
    float *scores, *eout;
    int *toklist, *counts;
    cudaGetSymbolAddress((void**)&hi,      g_hiA);
    cudaGetSymbolAddress((void**)&lo,      g_loA);
    cudaGetSymbolAddress((void**)&scores,  g_scores);
    cudaGetSymbolAddress((void**)&eout,    g_eout);
    cudaGetSymbolAddress((void**)&toklist, g_toklist);
    cudaGetSymbolAddress((void**)&counts,  g_counts);

    cudaFuncSetAttribute(hmma_gemm<0, 0>, cudaFuncAttributeMaxDynamicSharedMemorySize, SMEM_BYTES);
    cudaFuncSetAttribute(hmma_gemm<0, 1>, cudaFuncAttributeMaxDynamicSharedMemorySize, SMEM_BYTES);
    cudaFuncSetAttribute(hmma_gemm<0, 2>, cudaFuncAttributeMaxDynamicSharedMemorySize, SMEM_BYTES);
    cudaFuncSetAttribute(hmma_gemm<2, 2>, cudaFuncAttributeMaxDynamicSharedMemorySize, SMEM_BYTES);

    // 0) pre-split all static inputs into bf16 hi/lo planes
    struct CvtJob { const float* src; size_t off; size_t n; };
    const CvtJob jobs[7] = {
        {x,      X_OFF,   (size_t)X_SZ},
        {fc1_w,  FC1_OFF, (size_t)FC1_SZ},
        {fc2_w,  FC2_OFF, (size_t)FC2_SZ},
        {w1,     W1_OFF,  W1_SZ},
        {w2,     W2_OFF,  W2_SZ},
        {sw1,    SW1_OFF, (size_t)SW1_SZ},
        {sw2,    SW2_OFF, (size_t)SW2_SZ},
    };
    for (int j = 0; j < 7; j++) {
        int n4 = (int)(jobs[j].n / 4);
        cvt_kernel<<<(n4 + 255) / 256, 256>>>(
            (const float4*)jobs[j].src,
            (uint2*)(hi + jobs[j].off), (uint2*)(lo + jobs[j].off), n4);
    }

    // 1) gate (SIMT fp32): scores = sigmoid(x @ gate_w^T)
    gemm_bt<1><<<dim3(1, T_ / 128, 1), 256>>>(x, gate_w, scores, T_, E_, D_);

    // 2) routing + dispatch
    routing_kernel<<<T_ / 256, 256>>>(scores, gate_b);
    zero_counts_kernel<<<1, E_>>>();
    dispatch_kernel<<<(T_ * TOPK + 255) / 256, 256>>>();

    // 3) xl = x @ fc1_w^T  -> planes
    hmma_gemm<0, 2><<<dim3(DL_ / 128, T_ / 128, 1), 256, SMEM_BYTES>>>(
        hi + X_OFF, lo + X_OFF, hi + FC1_OFF, lo + FC1_OFF,
        nullptr, hi + XL_OFF, lo + XL_OFF,
        T_, DL_, D_, 0, 0, 0, nullptr, 0, nullptr);

    // 4) expert fc1: h[e] = relu2( gather(xl) @ w1[e]^T ) -> planes
    hmma_gemm<2, 2><<<dim3(I_ / 128, CAP_ / 128, E_), 256, SMEM_BYTES>>>(
        hi + XL_OFF, lo + XL_OFF, hi + W1_OFF, lo + W1_OFF,
        nullptr, hi + H_OFF, lo + H_OFF,
        CAP_, I_, DL_, 0, (long)I_ * DL_, (long)CAP_ * I_, toklist, CAP_, counts);

    // 5) expert fc2: eout[e] = h[e] @ w2[e]^T -> fp32
    hmma_gemm<0, 0><<<dim3(DL_ / 128, CAP_ / 128, E_), 256, SMEM_BYTES>>>(
        hi + H_OFF, lo + H_OFF, hi + W2_OFF, lo + W2_OFF,
        eout, nullptr, nullptr,
        CAP_, DL_, I_, (long)CAP_ * I_, (long)DL_ * I_, (long)CAP_ * DL_,
        nullptr, 0, counts);

    // 6) combine -> routed planes
    combine_kernel<<<(T_ * (DL_ / 4) + 255) / 256, 256>>>(hi + R_OFF, lo + R_OFF);

    // 7) s1 = relu2(x @ sw1^T) -> planes
    hmma_gemm<2, 2><<<dim3(SI_ / 128, T_ / 128, 1), 256, SMEM_BYTES>>>(
        hi + X_OFF, lo + X_OFF, hi + SW1_OFF, lo + SW1_OFF,
        nullptr, hi + S1_OFF, lo + S1_OFF,
        T_, SI_, D_, 0, 0, 0, nullptr, 0, nullptr);

    // 8) out = s1 @ sw2^T -> fp32
    hmma_gemm<0, 0><<<dim3(D_ / 128, T_ / 128, 1), 256, SMEM_BYTES>>>(
        hi + S1_OFF, lo + S1_OFF, hi + SW2_OFF, lo + SW2_OFF,
        out, nullptr, nullptr,
        T_, D_, SI_, 0, 0, 0, nullptr, 0, nullptr);

    // 9) out += routed @ fc2_w^T
    hmma_gemm<0, 1><<<dim3(D_ / 128, T_ / 128, 1), 256, SMEM_BYTES>>>(
        hi + R_OFF, lo + R_OFF, hi + FC2_OFF, lo + FC2_OFF,
        out, nullptr, nullptr,
        T_, D_, DL_, 0, 0, 0, nullptr, 0, nullptr);
}

// round 13
// speedup vs baseline: 1.0693x; 1.0693x over previous
#include <cuda_runtime.h>
#include <math.h>
#include <stdint.h>

// ---------------- problem constants ----------------
#define T_      2048
#define D_      2048
#define DL_     1024
#define E_      64
#define I_      768
#define SI_     4096
#define TOPK    6
#define NGROUP  8
#define GSIZE   8
#define TOPKG   4
#define CAP_    384
#define RSCALE  2.5f

// ---------------- scratch (device globals; no allocs allowed) ----------------
__device__ float g_scores[T_ * E_];
__device__ float g_xl[T_ * DL_];
__device__ float g_s1[(size_t)T_ * SI_];
__device__ float g_h[(size_t)E_ * CAP_ * I_];
__device__ float g_eout[(size_t)E_ * CAP_ * DL_];
__device__ float g_routed[T_ * DL_];
__device__ int   g_tidx[T_ * TOPK];
__device__ float g_tw[T_ * TOPK];
__device__ int   g_counts[E_];
__device__ int   g_toklist[E_ * CAP_];
__device__ int   g_slot[T_ * TOPK];

// =====================================================================
// helpers
// =====================================================================
__device__ __forceinline__ uint32_t smem_u32(const void* p) {
    uint32_t a;
    asm("{ .reg .u64 t; cvta.to.shared.u64 t, %1; cvt.u32.u64 %0, t; }" : "=r"(a) : "l"(p));
    return a;
}
__device__ __forceinline__ uint32_t pack_bf2(float lo, float hi) {
    uint32_t r;
    asm("cvt.rn.bf16x2.f32 %0, %1, %2;" : "=r"(r) : "f"(hi), "f"(lo));
    return r;
}
__device__ __forceinline__ void split4(float4 v, uint2& h, uint2& l) {
    h.x = pack_bf2(v.x, v.y); h.y = pack_bf2(v.z, v.w);
    float f0 = __uint_as_float(h.x << 16), f1 = __uint_as_float(h.x & 0xffff0000u);
    float f2 = __uint_as_float(h.y << 16), f3 = __uint_as_float(h.y & 0xffff0000u);
    l.x = pack_bf2(v.x - f0, v.y - f1); l.y = pack_bf2(v.z - f2, v.w - f3);
}
__device__ __forceinline__ void ldm_x4(uint32_t* r, uint32_t a) {
    asm volatile("ldmatrix.sync.aligned.m8n8.x4.shared.b16 {%0,%1,%2,%3}, [%4];"
                 : "=r"(r[0]), "=r"(r[1]), "=r"(r[2]), "=r"(r[3]) : "r"(a));
}
__device__ __forceinline__ void mma_bf16(float* d, const uint32_t* a, uint32_t b0, uint32_t b1) {
    asm volatile(
        "mma.sync.aligned.m16n8k16.row.col.f32.bf16.bf16.f32 "
        "{%0,%1,%2,%3},{%4,%5,%6,%7},{%8,%9},{%0,%1,%2,%3};"
        : "+f"(d[0]), "+f"(d[1]), "+f"(d[2]), "+f"(d[3])
        : "r"(a[0]), "r"(a[1]), "r"(a[2]), "r"(a[3]), "r"(b0), "r"(b1));
}

// smem stage: 4 bf16 tiles of 128 rows x 32 cols, row stride 80B
// (80B stride => ldmatrix rows land in distinct bank phases)
#define RSTRIDE 80
#define AHI_OFF 0
#define ALO_OFF 10240
#define BHI_OFF 20480
#define BLO_OFF 30720
#define STAGE_B 40960
#define SMEM_BYTES (2 * STAGE_B)

// =====================================================================
// split-bf16 HMMA GEMM: C[z] = epi( A[z](gathered rows) * B[z]^T )
// A:[M,K] fp32, B:[N,K] fp32, C:[M,N]. 128x128x32 CTA tile, 512 threads.
// 16 warps (4M x 4N), warp tile 32x32, mma.m16n8k16, fp32 accum, 3-MMA.
// One __syncthreads per k-chunk (R6 ordering), G2R prefetch + fused split.
// =====================================================================
template <int EPI, bool ACC>
__global__ __launch_bounds__(512, 1)
void hmma_gemm(const float* __restrict__ Ab, const float* __restrict__ Bb,
               float* __restrict__ Cb, int M, int N, int K,
               long sAz, long sBz, long sCz,
               const int* __restrict__ gatherB, long sGz,
               const int* __restrict__ counts)
{
    extern __shared__ char sm[];
    const int z = blockIdx.z;
    const float* A = Ab + (size_t)z * sAz;
    const float* B = Bb + (size_t)z * sBz;
    float*       C = Cb + (size_t)z * sCz;
    const int* g = gatherB ? (gatherB + (size_t)z * sGz) : nullptr;

    int rowLimit = M;
    if (counts) { int c = counts[z]; rowLimit = (c < M) ? c : M; }
    const int m0 = blockIdx.y * 128;
    const int n0 = blockIdx.x * 128;
    if (m0 >= rowLimit) return;

    const uint32_t sbase = smem_u32(sm);
    const int tid  = threadIdx.x;
    const int lane = tid & 31;
    const int wid  = tid >> 5;
    const int warp_m = wid & 3;       // 4 warps along M (32 rows each)
    const int warp_n = wid >> 2;      // 4 warps along N (32 cols each)

    // ---- gmem loader: 2 rows x 1 float4 per thread per matrix ----
    const int colf4 = tid & 7;        // float4 index within 32-float chunk
    const int rg    = tid >> 3;       // 0..63
    const float4* ap[2];
    const float4* bp[2];
#pragma unroll
    for (int it = 0; it < 2; it++) {
        int row = rg + 64 * it;
        int ar = m0 + row;
        if (ar < rowLimit) {
            int src = g ? g[ar] : ar;
            ap[it] = (const float4*)(A + (size_t)src * K) + colf4;
        } else ap[it] = nullptr;
        bp[it] = (const float4*)(B + (size_t)(n0 + row) * K) + colf4;
    }

    const int KT = K >> 5;            // chunks of 32 floats
    float4 ra[2], rb[2];
#pragma unroll
    for (int it = 0; it < 2; it++) {
        ra[it] = ap[it] ? __ldg(ap[it]) : make_float4(0, 0, 0, 0);
        rb[it] = __ldg(bp[it]);
    }

    float acc[2][4][4];
#pragma unroll
    for (int im = 0; im < 2; im++)
#pragma unroll
        for (int in = 0; in < 4; in++)
#pragma unroll
            for (int q = 0; q < 4; q++) acc[im][in][q] = 0.f;

    // store chunk 0 into stage 0
    {
        char* st = sm;
#pragma unroll
        for (int it = 0; it < 2; it++) {
            int row = rg + 64 * it;
            uint32_t off = row * RSTRIDE + colf4 * 8;
            uint2 h, l;
            split4(ra[it], h, l);
            *(uint2*)(st + AHI_OFF + off) = h;
            *(uint2*)(st + ALO_OFF + off) = l;
            split4(rb[it], h, l);
            *(uint2*)(st + BHI_OFF + off) = h;
            *(uint2*)(st + BLO_OFF + off) = l;
        }
    }
    __syncthreads();

    // B ldmatrix address components: x4 covers 16 n-cols (k0 & k8 halves)
    const int bt   = lane >> 3;       // 0..3
    const int brow = lane & 7;
    const uint32_t bn_off = (uint32_t)((warp_n * 32 + ((bt >> 1) * 8) + brow) * RSTRIDE
                                       + (bt & 1) * 16);

    for (int kt = 0; kt < KT; ++kt) {
        const int cur = kt & 1;
        const bool more = (kt + 1 < KT);
        if (more) {
#pragma unroll
            for (int it = 0; it < 2; it++) {
                ra[it] = ap[it] ? __ldg(ap[it] + (kt + 1) * 8) : make_float4(0, 0, 0, 0);
                rb[it] = __ldg(bp[it] + (kt + 1) * 8);
            }
        }

        // ---- MMA on stage cur ----
        const uint32_t sb = sbase + (cur ? STAGE_B : 0);
#pragma unroll
        for (int k16 = 0; k16 < 2; k16++) {
            uint32_t ah[2][4], al[2][4];
#pragma unroll
            for (int im = 0; im < 2; im++) {
                uint32_t row = warp_m * 32 + im * 16 + (lane & 15);
                uint32_t addr = sb + row * RSTRIDE + k16 * 32 + (lane >> 4) * 16;
                ldm_x4(ah[im], addr + AHI_OFF);
                ldm_x4(al[im], addr + ALO_OFF);
            }
#pragma unroll
            for (int gp = 0; gp < 2; gp++) {     // each x4 covers 16 n-cols
                uint32_t addr = sb + bn_off + gp * 16 * RSTRIDE + k16 * 32;
                uint32_t bh4[4], bl4[4];
                ldm_x4(bh4, addr + BHI_OFF);
                ldm_x4(bl4, addr + BLO_OFF);
#pragma unroll
                for (int j = 0; j < 2; j++) {
                    const int in = 2 * gp + j;
#pragma unroll
                    for (int im = 0; im < 2; im++) {
                        mma_bf16(acc[im][in], ah[im], bh4[2 * j], bh4[2 * j + 1]);
                        mma_bf16(acc[im][in], ah[im], bl4[2 * j], bl4[2 * j + 1]);
                        mma_bf16(acc[im][in], al[im], bh4[2 * j], bh4[2 * j + 1]);
                    }
                }
            }
        }

        if (more) {
            char* st = sm + (cur ? 0 : STAGE_B);   // write other stage
#pragma unroll
            for (int it = 0; it < 2; it++) {
                int row = rg + 64 * it;
                uint32_t off = row * RSTRIDE + colf4 * 8;
                uint2 h, l;
                split4(ra[it], h, l);
                *(uint2*)(st + AHI_OFF + off) = h;
                *(uint2*)(st + ALO_OFF + off) = l;
                split4(rb[it], h, l);
                *(uint2*)(st + BHI_OFF + off) = h;
                *(uint2*)(st + BLO_OFF + off) = l;
            }
            __syncthreads();
        }
    }

    // ---- epilogue ----
#pragma unroll
    for (int im = 0; im < 2; im++) {
        int row0 = m0 + warp_m * 32 + im * 16 + (lane >> 2);
#pragma unroll
        for (int half = 0; half < 2; half++) {
            int r = row0 + half * 8;
            float* crow = C + (size_t)r * N;
#pragma unroll
            for (int in = 0; in < 4; in++) {
                int col = n0 + warp_n * 32 + in * 8 + (lane & 3) * 2;
                float x0 = acc[im][in][half * 2 + 0];
                float x1 = acc[im][in][half * 2 + 1];
                if (EPI == 2) {
                    float r0 = fmaxf(x0, 0.f), r1 = fmaxf(x1, 0.f);
                    x0 = r0 * r0; x1 = r1 * r1;
                }
                if (ACC) {
                    float2 old = *(const float2*)(crow + col);
                    x0 += old.x; x1 += old.y;
                }
                *(float2*)(crow + col) = make_float2(x0, x1);
            }
        }
    }
}

// =====================================================================
// SIMT GEMM for the gate (N=64 only)
// =====================================================================
template <int EPI>
__global__ __launch_bounds__(256, 2)
void gemm_bt(const float* __restrict__ A, const float* __restrict__ B,
             float* __restrict__ C, int M, int N, int K)
{
    const int m0 = blockIdx.y * 128;
    const int n0 = blockIdx.x * 128;
    __shared__ float As[2][8][132];
    __shared__ float Bs[2][8][132];
    const int tid = threadIdx.x;
    const int tx = tid & 15, ty = tid >> 4;
    const int lr = tid >> 1, lk = (tid & 1) * 4;
    float acc[8][8];
#pragma unroll
    for (int i = 0; i < 8; i++)
#pragma unroll
        for (int j = 0; j < 8; j++) acc[i][j] = 0.f;
    const int KT = K >> 3;
    const float* Arow = (m0 + lr < M) ? A + (size_t)(m0 + lr) * K : nullptr;
    const float* Brow = (n0 + lr < N) ? B + (size_t)(n0 + lr) * K : nullptr;
    {
        float4 va = Arow ? *(const float4*)(Arow + lk) : make_float4(0, 0, 0, 0);
        float4 vb = Brow ? *(const float4*)(Brow + lk) : make_float4(0, 0, 0, 0);
        As[0][lk][lr] = va.x; As[0][lk + 1][lr] = va.y; As[0][lk + 2][lr] = va.z; As[0][lk + 3][lr] = va.w;
        Bs[0][lk][lr] = vb.x; Bs[0][lk + 1][lr] = vb.y; Bs[0][lk + 2][lr] = vb.z; Bs[0][lk + 3][lr] = vb.w;
    }
    __syncthreads();
    for (int kt = 0; kt < KT; ++kt) {
        const int cur = kt & 1, nxt = cur ^ 1;
        float4 va = make_float4(0, 0, 0, 0), vb = make_float4(0, 0, 0, 0);
        const bool more = (kt + 1 < KT);
        if (more) {
            int k0 = (kt + 1) << 3;
            if (Arow) va = *(const float4*)(Arow + k0 + lk);
            if (Brow) vb = *(const float4*)(Brow + k0 + lk);
        }
#pragma unroll
        for (int k = 0; k < 8; k++) {
            float4 a0 = *(const float4*)&As[cur][k][ty * 4];
            float4 a1 = *(const float4*)&As[cur][k][64 + ty * 4];
            float4 b0 = *(const float4*)&Bs[cur][k][tx * 4];
            float4 b1 = *(const float4*)&Bs[cur][k][64 + tx * 4];
            float a[8] = {a0.x, a0.y, a0.z, a0.w, a1.x, a1.y, a1.z, a1.w};
            float b[8] = {b0.x, b0.y, b0.z, b0.w, b1.x, b1.y, b1.z, b1.w};
#pragma unroll
            for (int i = 0; i < 8; i++)
#pragma unroll
                for (int j = 0; j < 8; j++) acc[i][j] += a[i] * b[j];
        }
        if (more) {
            As[nxt][lk][lr] = va.x; As[nxt][lk + 1][lr] = va.y; As[nxt][lk + 2][lr] = va.z; As[nxt][lk + 3][lr] = va.w;
            Bs[nxt][lk][lr] = vb.x; Bs[nxt][lk + 1][lr] = vb.y; Bs[nxt][lk + 2][lr] = vb.z; Bs[nxt][lk + 3][lr] = vb.w;
        }
        __syncthreads();
    }
#pragma unroll
    for (int ri = 0; ri < 2; ri++)
#pragma unroll
        for (int i = 0; i < 4; i++) {
            int r = m0 + ri * 64 + ty * 4 + i;
            if (r >= M) continue;
            float* Crow = C + (size_t)r * N;
#pragma unroll
            for (int ci = 0; ci < 2; ci++) {
                int c = n0 + ci * 64 + tx * 4;
                if (c >= N) continue;
                float v[4];
#pragma unroll
                for (int j = 0; j < 4; j++) {
                    float x = acc[ri * 4 + i][ci * 4 + j];
                    if (EPI == 1) x = 1.f / (1.f + expf(-x));
                    v[j] = x;
                }
                *(float4*)(Crow + c) = make_float4(v[0], v[1], v[2], v[3]);
            }
        }
}

// ================================================================
// routing / dispatch / combine
// ================================================================
__global__ void routing_kernel(const float* __restrict__ scores,
                               const float* __restrict__ bias)
{
    int t = blockIdx.x * blockDim.x + threadIdx.x;
    if (t >= T_) return;
    float s[E_], m[E_];
    const float* sr = scores + t * E_;
#pragma unroll
    for (int e = 0; e < E_; e++) s[e] = sr[e];
    float gs[NGROUP];
    for (int gi = 0; gi < NGROUP; gi++) {
        float m1 = -1e30f, m2 = -1e30f;
        for (int j = 0; j < GSIZE; j++) {
            float v = s[gi * GSIZE + j] + bias[gi * GSIZE + j];
            if (v > m1) { m2 = m1; m1 = v; } else if (v > m2) m2 = v;
        }
        gs[gi] = m1 + m2;
    }
    bool gsel[NGROUP];
    for (int gi = 0; gi < NGROUP; gi++) gsel[gi] = false;
    for (int it = 0; it < TOPKG; it++) {
        float best = -1e30f; int bi = 0;
        for (int gi = 0; gi < NGROUP; gi++)
            if (!gsel[gi] && gs[gi] > best) { best = gs[gi]; bi = gi; }
        gsel[bi] = true;
    }
    for (int e = 0; e < E_; e++)
        m[e] = gsel[e / GSIZE] ? (s[e] + bias[e]) : 0.0f;
    float wsum = 0.f;
    int sel_e[TOPK]; float sel_w[TOPK];
    for (int k = 0; k < TOPK; k++) {
        float best = -1e30f; int bi = 0;
        for (int e = 0; e < E_; e++)
            if (m[e] > best) { best = m[e]; bi = e; }
        m[bi] = -1e30f;
        sel_e[k] = bi; sel_w[k] = s[bi]; wsum += s[bi];
    }
    float inv = RSCALE / (wsum + 1e-20f);
    for (int k = 0; k < TOPK; k++) {
        g_tidx[t * TOPK + k] = sel_e[k];
        g_tw[t * TOPK + k] = sel_w[k] * inv;
    }
}

__global__ void zero_counts_kernel()
{
    if (threadIdx.x < E_) g_counts[threadIdx.x] = 0;
}

__global__ void dispatch_kernel()
{
    int i = blockIdx.x * blockDim.x + threadIdx.x;
    if (i >= T_ * TOPK) return;
    int e = g_tidx[i];
    int p = atomicAdd(&g_counts[e], 1);
    if (p < CAP_) {
        int sl = e * CAP_ + p;
        g_toklist[sl] = i / TOPK;
        g_slot[i] = sl;
    } else g_slot[i] = -1;
}

__global__ void combine_kernel()
{
    const int nd4 = DL_ / 4;
    int idx = blockIdx.x * blockDim.x + threadIdx.x;
    if (idx >= T_ * nd4) return;
    int t = idx / nd4, d4 = idx % nd4;
    float4 acc = make_float4(0, 0, 0, 0);
#pragma unroll
    for (int k = 0; k < TOPK; k++) {
        int s = g_slot[t * TOPK + k];
        if (s >= 0) {
            float w = g_tw[t * TOPK + k];
            float4 v = *(const float4*)(g_eout + (size_t)s * DL_ + d4 * 4);
            acc.x += w * v.x; acc.y += w * v.y;
            acc.z += w * v.z; acc.w += w * v.w;
        }
    }
    *(float4*)(g_routed + (size_t)t * DL_ + d4 * 4) = acc;
}

// ================================================================
extern "C" void kernel_launch(void* const* d_in, const int* in_sizes, int n_in,
                              void* d_out, int out_size)
{
    (void)in_sizes; (void)n_in; (void)out_size;
    const float* x      = (const float*)d_in[0];
    const float* gate_w = (const float*)d_in[1];
    const float* gate_b = (const float*)d_in[2];
    const float* fc1_w  = (const float*)d_in[3];
    const float* fc2_w  = (const float*)d_in[4];
    const float* w1     = (const float*)d_in[5];
    const float* w2     = (const float*)d_in[6];
    const float* sw1    = (const float*)d_in[7];
    const float* sw2    = (const float*)d_in[8];
    float* out = (float*)d_out;

    float *scores, *xl, *s1, *h, *eout, *routed;
    int *toklist, *counts;
    cudaGetSymbolAddress((void**)&scores,  g_scores);
    cudaGetSymbolAddress((void**)&xl,      g_xl);
    cudaGetSymbolAddress((void**)&s1,      g_s1);
    cudaGetSymbolAddress((void**)&h,       g_h);
    cudaGetSymbolAddress((void**)&eout,    g_eout);
    cudaGetSymbolAddress((void**)&toklist, g_toklist);
    cudaGetSymbolAddress((void**)&routed,  g_routed);
    cudaGetSymbolAddress((void**)&counts,  g_counts);

    cudaFuncSetAttribute(hmma_gemm<0, false>, cudaFuncAttributeMaxDynamicSharedMemorySize, SMEM_BYTES);
    cudaFuncSetAttribute(hmma_gemm<2, false>, cudaFuncAttributeMaxDynamicSharedMemorySize, SMEM_BYTES);
    cudaFuncSetAttribute(hmma_gemm<0, true >, cudaFuncAttributeMaxDynamicSharedMemorySize, SMEM_BYTES);

    // 1) gate (SIMT, N=64): scores = sigmoid(x @ gate_w^T)
    gemm_bt<1><<<dim3(1, T_ / 128, 1), 256>>>(x, gate_w, scores, T_, E_, D_);

    // 2) routing + dispatch
    routing_kernel<<<T_ / 256, 256>>>(scores, gate_b);
    zero_counts_kernel<<<1, E_>>>();
    dispatch_kernel<<<(T_ * TOPK + 255) / 256, 256>>>();

    // 3) latent down-projection: xl = x @ fc1_w^T
    hmma_gemm<0, false><<<dim3(DL_ / 128, T_ / 128, 1), 512, SMEM_BYTES>>>(
        x, fc1_w, xl, T_, DL_, D_, 0, 0, 0, nullptr, 0, nullptr);

    // 4) expert fc1: h[e] = relu2( gather(xl) @ w1[e]^T )
    hmma_gemm<2, false><<<dim3(I_ / 128, CAP_ / 128, E_), 512, SMEM_BYTES>>>(
        xl, w1, h, CAP_, I_, DL_,
        0, (long)I_ * DL_, (long)CAP_ * I_, toklist, CAP_, counts);

    // 5) expert fc2: eout[e] = h[e] @ w2[e]^T
    hmma_gemm<0, false><<<dim3(DL_ / 128, CAP_ / 128, E_), 512, SMEM_BYTES>>>(
        h, w2, eout, CAP_, DL_, I_,
        (long)CAP_ * I_, (long)DL_ * I_, (long)CAP_ * DL_, nullptr, 0, counts);

    // 6) combine
    combine_kernel<<<(T_ * (DL_ / 4) + 255) / 256, 256>>>();

    // 7) shared hidden: s1 = relu2(x @ sw1^T)
    hmma_gemm<2, false><<<dim3(SI_ / 128, T_ / 128, 1), 512, SMEM_BYTES>>>(
        x, sw1, s1, T_, SI_, D_, 0, 0, 0, nullptr, 0, nullptr);

    // 8) out = s1 @ sw2^T
    hmma_gemm<0, false><<<dim3(D_ / 128, T_ / 128, 1), 512, SMEM_BYTES>>>(
        s1, sw2, out, T_, D_, SI_, 0, 0, 0, nullptr, 0, nullptr);

    // 9) out += routed @ fc2_w^T
    hmma_gemm<0, true><<<dim3(D_ / 128, T_ / 128, 1), 512, SMEM_BYTES>>>(
        routed, fc2_w, out, T_, D_, DL_, 0, 0, 0, nullptr, 0, nullptr);
}

// round 14
// speedup vs baseline: 1.1938x; 1.1165x over previous
#include <cuda_runtime.h>
#include <math.h>
#include <stdint.h>

// ---------------- problem constants ----------------
#define T_      2048
#define D_      2048
#define DL_     1024
#define E_      64
#define I_      768
#define SI_     4096
#define TOPK    6
#define NGROUP  8
#define GSIZE   8
#define TOPKG   4
#define CAP_    384
#define RSCALE  2.5f

// ---------------- scratch (device globals; no allocs allowed) ----------------
__device__ float g_scores[T_ * E_];
__device__ float g_xl[T_ * DL_];
__device__ float g_s1[(size_t)T_ * SI_];
__device__ float g_h[(size_t)E_ * CAP_ * I_];
__device__ float g_eout[(size_t)E_ * CAP_ * DL_];
__device__ float g_routed[T_ * DL_];
__device__ int   g_tidx[T_ * TOPK];
__device__ float g_tw[T_ * TOPK];
__device__ int   g_counts[E_];
__device__ int   g_toklist[E_ * CAP_];
__device__ int   g_slot[T_ * TOPK];

// =====================================================================
// helpers
// =====================================================================
__device__ __forceinline__ uint32_t smem_u32(const void* p) {
    uint32_t a;
    asm("{ .reg .u64 t; cvta.to.shared.u64 t, %1; cvt.u32.u64 %0, t; }" : "=r"(a) : "l"(p));
    return a;
}
__device__ __forceinline__ uint32_t pack_bf2(float lo, float hi) {
    uint32_t r;
    asm("cvt.rn.bf16x2.f32 %0, %1, %2;" : "=r"(r) : "f"(hi), "f"(lo));
    return r;
}
__device__ __forceinline__ void split4(float4 v, uint2& h, uint2& l) {
    h.x = pack_bf2(v.x, v.y); h.y = pack_bf2(v.z, v.w);
    float f0 = __uint_as_float(h.x << 16), f1 = __uint_as_float(h.x & 0xffff0000u);
    float f2 = __uint_as_float(h.y << 16), f3 = __uint_as_float(h.y & 0xffff0000u);
    l.x = pack_bf2(v.x - f0, v.y - f1); l.y = pack_bf2(v.z - f2, v.w - f3);
}
__device__ __forceinline__ void ldm_x4(uint32_t* r, uint32_t a) {
    asm volatile("ldmatrix.sync.aligned.m8n8.x4.shared.b16 {%0,%1,%2,%3}, [%4];"
                 : "=r"(r[0]), "=r"(r[1]), "=r"(r[2]), "=r"(r[3]) : "r"(a));
}
__device__ __forceinline__ void mma_bf16(float* d, const uint32_t* a, uint32_t b0, uint32_t b1) {
    asm volatile(
        "mma.sync.aligned.m16n8k16.row.col.f32.bf16.bf16.f32 "
        "{%0,%1,%2,%3},{%4,%5,%6,%7},{%8,%9},{%0,%1,%2,%3};"
        : "+f"(d[0]), "+f"(d[1]), "+f"(d[2]), "+f"(d[3])
        : "r"(a[0]), "r"(a[1]), "r"(a[2]), "r"(a[3]), "r"(b0), "r"(b1));
}

// smem stage: 4 bf16 tiles of 128 rows x 32 cols, row stride 80B
// (80B stride => ldmatrix rows land in distinct bank phases)
#define RSTRIDE 80
#define AHI_OFF 0
#define ALO_OFF 10240
#define BHI_OFF 20480
#define BLO_OFF 30720
#define STAGE_B 40960
#define SMEM_BYTES (2 * STAGE_B)

// =====================================================================
// split-bf16 HMMA GEMM: C[z] = epi( A[z](gathered rows) * B[z]^T )
// A:[M,K] fp32, B:[N,K] fp32, C:[M,N]. 128x128x32 tiles, 256 threads.
// 8 warps (4M x 2N), warp tile 32x64, mma.m16n8k16, fp32 accum, 3-MMA.
// Fragment software pipelining: A frags for both k16 preloaded; B frags
// double-buffered one gp-group ahead of their MMAs.
// =====================================================================
template <int EPI, bool ACC>
__global__ __launch_bounds__(256, 1)
void hmma_gemm(const float* __restrict__ Ab, const float* __restrict__ Bb,
               float* __restrict__ Cb, int M, int N, int K,
               long sAz, long sBz, long sCz,
               const int* __restrict__ gatherB, long sGz,
               const int* __restrict__ counts)
{
    extern __shared__ char sm[];
    const int z = blockIdx.z;
    const float* A = Ab + (size_t)z * sAz;
    const float* B = Bb + (size_t)z * sBz;
    float*       C = Cb + (size_t)z * sCz;
    const int* g = gatherB ? (gatherB + (size_t)z * sGz) : nullptr;

    int rowLimit = M;
    if (counts) { int c = counts[z]; rowLimit = (c < M) ? c : M; }
    const int m0 = blockIdx.y * 128;
    const int n0 = blockIdx.x * 128;
    if (m0 >= rowLimit) return;

    const uint32_t sbase = smem_u32(sm);
    const int tid  = threadIdx.x;
    const int lane = tid & 31;
    const int wid  = tid >> 5;
    const int warp_m = wid & 3;       // 4 warps along M (32 rows each)
    const int warp_n = wid >> 2;      // 2 warps along N (64 cols each)

    // ---- gmem loader mapping: 4 rows x 1 float4 per thread per matrix ----
    const int colf4 = tid & 7;
    const int rg    = tid >> 3;
    const float4* ap[4];
    const float4* bp[4];
#pragma unroll
    for (int it = 0; it < 4; it++) {
        int row = rg + 32 * it;
        int ar = m0 + row;
        if (ar < rowLimit) {
            int src = g ? g[ar] : ar;
            ap[it] = (const float4*)(A + (size_t)src * K) + colf4;
        } else ap[it] = nullptr;
        bp[it] = (const float4*)(B + (size_t)(n0 + row) * K) + colf4;
    }

    const int KT = K >> 5;
    float4 ra[4], rb[4];
#pragma unroll
    for (int it = 0; it < 4; it++) {
        ra[it] = ap[it] ? __ldg(ap[it]) : make_float4(0, 0, 0, 0);
        rb[it] = __ldg(bp[it]);
    }

    float acc[2][8][4];
#pragma unroll
    for (int im = 0; im < 2; im++)
#pragma unroll
        for (int in = 0; in < 8; in++)
#pragma unroll
            for (int q = 0; q < 4; q++) acc[im][in][q] = 0.f;

    // store chunk 0 into stage 0
    {
        char* st = sm;
#pragma unroll
        for (int it = 0; it < 4; it++) {
            int row = rg + 32 * it;
            uint32_t off = row * RSTRIDE + colf4 * 8;
            uint2 h, l;
            split4(ra[it], h, l);
            *(uint2*)(st + AHI_OFF + off) = h;
            *(uint2*)(st + ALO_OFF + off) = l;
            split4(rb[it], h, l);
            *(uint2*)(st + BHI_OFF + off) = h;
            *(uint2*)(st + BLO_OFF + off) = l;
        }
    }
    __syncthreads();

    // A ldmatrix base (per thread): row within warp M block + k16/plane offsets
    const uint32_t an_row = (uint32_t)(warp_m * 32 + (lane & 15));
    const uint32_t a_base = an_row * RSTRIDE + (lane >> 4) * 16;

    // B ldmatrix address components: x4 covers 16 n-cols (both k-halves of k16)
    const int bt   = lane >> 3;
    const int brow = lane & 7;
    const uint32_t bn_off = (uint32_t)((warp_n * 64 + ((bt >> 1) * 8) + brow) * RSTRIDE
                                       + (bt & 1) * 16);

    for (int kt = 0; kt < KT; ++kt) {
        const int cur = kt & 1;
        const bool more = (kt + 1 < KT);
        if (more) {
#pragma unroll
            for (int it = 0; it < 4; it++) {
                ra[it] = ap[it] ? __ldg(ap[it] + (kt + 1) * 8) : make_float4(0, 0, 0, 0);
                rb[it] = __ldg(bp[it] + (kt + 1) * 8);
            }
        }

        // ---- MMA on stage cur, software-pipelined fragments ----
        const uint32_t sb = sbase + (cur ? STAGE_B : 0);

        // preload A fragments for BOTH k16 halves
        uint32_t ah[2][2][4], al[2][2][4];   // [k16][im][4]
#pragma unroll
        for (int k16 = 0; k16 < 2; k16++)
#pragma unroll
            for (int im = 0; im < 2; im++) {
                uint32_t addr = sb + a_base + im * 16 * RSTRIDE + k16 * 32;
                ldm_x4(ah[k16][im], addr + AHI_OFF);
                ldm_x4(al[k16][im], addr + ALO_OFF);
            }

        // B double buffer, one gp-group ahead
        uint32_t bh_cur[4], bl_cur[4];
        {
            uint32_t addr = sb + bn_off;           // k16=0, gp=0
            ldm_x4(bh_cur, addr + BHI_OFF);
            ldm_x4(bl_cur, addr + BLO_OFF);
        }
#pragma unroll
        for (int k16 = 0; k16 < 2; k16++) {
#pragma unroll
            for (int gp = 0; gp < 4; gp++) {
                uint32_t bh_nxt[4], bl_nxt[4];
                const int last = (k16 == 1) && (gp == 3);
                if (!last) {
                    int ngp = (gp + 1) & 3;
                    int nk  = (gp == 3) ? 1 : k16;
                    uint32_t naddr = sb + bn_off + ngp * 16 * RSTRIDE + nk * 32;
                    ldm_x4(bh_nxt, naddr + BHI_OFF);
                    ldm_x4(bl_nxt, naddr + BLO_OFF);
                }
#pragma unroll
                for (int j = 0; j < 2; j++) {
                    const int in = 2 * gp + j;
#pragma unroll
                    for (int im = 0; im < 2; im++) {
                        mma_bf16(acc[im][in], ah[k16][im], bh_cur[2 * j], bh_cur[2 * j + 1]);
                        mma_bf16(acc[im][in], ah[k16][im], bl_cur[2 * j], bl_cur[2 * j + 1]);
                        mma_bf16(acc[im][in], al[k16][im], bh_cur[2 * j], bh_cur[2 * j + 1]);
                    }
                }
                if (!last) {
#pragma unroll
                    for (int q = 0; q < 4; q++) { bh_cur[q] = bh_nxt[q]; bl_cur[q] = bl_nxt[q]; }
                }
            }
        }

        if (more) {
            char* st = sm + (cur ? 0 : STAGE_B);
#pragma unroll
            for (int it = 0; it < 4; it++) {
                int row = rg + 32 * it;
                uint32_t off = row * RSTRIDE + colf4 * 8;
                uint2 h, l;
                split4(ra[it], h, l);
                *(uint2*)(st + AHI_OFF + off) = h;
                *(uint2*)(st + ALO_OFF + off) = l;
                split4(rb[it], h, l);
                *(uint2*)(st + BHI_OFF + off) = h;
                *(uint2*)(st + BLO_OFF + off) = l;
            }
            __syncthreads();
        }
    }

    // ---- epilogue ----
#pragma unroll
    for (int im = 0; im < 2; im++) {
        int row0 = m0 + warp_m * 32 + im * 16 + (lane >> 2);
#pragma unroll
        for (int half = 0; half < 2; half++) {
            int r = row0 + half * 8;
            float* crow = C + (size_t)r * N;
#pragma unroll
            for (int in = 0; in < 8; in++) {
                int col = n0 + warp_n * 64 + in * 8 + (lane & 3) * 2;
                float x0 = acc[im][in][half * 2 + 0];
                float x1 = acc[im][in][half * 2 + 1];
                if (EPI == 2) {
                    float r0 = fmaxf(x0, 0.f), r1 = fmaxf(x1, 0.f);
                    x0 = r0 * r0; x1 = r1 * r1;
                }
                if (ACC) {
                    float2 old = *(const float2*)(crow + col);
                    x0 += old.x; x1 += old.y;
                }
                *(float2*)(crow + col) = make_float2(x0, x1);
            }
        }
    }
}

// =====================================================================
// SIMT GEMM for the gate (N=64 only)
// =====================================================================
template <int EPI>
__global__ __launch_bounds__(256, 2)
void gemm_bt(const float* __restrict__ A, const float* __restrict__ B,
             float* __restrict__ C, int M, int N, int K)
{
    const int m0 = blockIdx.y * 128;
    const int n0 = blockIdx.x * 128;
    __shared__ float As[2][8][132];
    __shared__ float Bs[2][8][132];
    const int tid = threadIdx.x;
    const int tx = tid & 15, ty = tid >> 4;
    const int lr = tid >> 1, lk = (tid & 1) * 4;
    float acc[8][8];
#pragma unroll
    for (int i = 0; i < 8; i++)
#pragma unroll
        for (int j = 0; j < 8; j++) acc[i][j] = 0.f;
    const int KT = K >> 3;
    const float* Arow = (m0 + lr < M) ? A + (size_t)(m0 + lr) * K : nullptr;
    const float* Brow = (n0 + lr < N) ? B + (size_t)(n0 + lr) * K : nullptr;
    {
        float4 va = Arow ? *(const float4*)(Arow + lk) : make_float4(0, 0, 0, 0);
        float4 vb = Brow ? *(const float4*)(Brow + lk) : make_float4(0, 0, 0, 0);
        As[0][lk][lr] = va.x; As[0][lk + 1][lr] = va.y; As[0][lk + 2][lr] = va.z; As[0][lk + 3][lr] = va.w;
        Bs[0][lk][lr] = vb.x; Bs[0][lk + 1][lr] = vb.y; Bs[0][lk + 2][lr] = vb.z; Bs[0][lk + 3][lr] = vb.w;
    }
    __syncthreads();
    for (int kt = 0; kt < KT; ++kt) {
        const int cur = kt & 1, nxt = cur ^ 1;
        float4 va = make_float4(0, 0, 0, 0), vb = make_float4(0, 0, 0, 0);
        const bool more = (kt + 1 < KT);
        if (more) {
            int k0 = (kt + 1) << 3;
            if (Arow) va = *(const float4*)(Arow + k0 + lk);
            if (Brow) vb = *(const float4*)(Brow + k0 + lk);
        }
#pragma unroll
        for (int k = 0; k < 8; k++) {
            float4 a0 = *(const float4*)&As[cur][k][ty * 4];
            float4 a1 = *(const float4*)&As[cur][k][64 + ty * 4];
            float4 b0 = *(const float4*)&Bs[cur][k][tx * 4];
            float4 b1 = *(const float4*)&Bs[cur][k][64 + tx * 4];
            float a[8] = {a0.x, a0.y, a0.z, a0.w, a1.x, a1.y, a1.z, a1.w};
            float b[8] = {b0.x, b0.y, b0.z, b0.w, b1.x, b1.y, b1.z, b1.w};
#pragma unroll
            for (int i = 0; i < 8; i++)
#pragma unroll
                for (int j = 0; j < 8; j++) acc[i][j] += a[i] * b[j];
        }
        if (more) {
            As[nxt][lk][lr] = va.x; As[nxt][lk + 1][lr] = va.y; As[nxt][lk + 2][lr] = va.z; As[nxt][lk + 3][lr] = va.w;
            Bs[nxt][lk][lr] = vb.x; Bs[nxt][lk + 1][lr] = vb.y; Bs[nxt][lk + 2][lr] = vb.z; Bs[nxt][lk + 3][lr] = vb.w;
        }
        __syncthreads();
    }
#pragma unroll
    for (int ri = 0; ri < 2; ri++)
#pragma unroll
        for (int i = 0; i < 4; i++) {
            int r = m0 + ri * 64 + ty * 4 + i;
            if (r >= M) continue;
            float* Crow = C + (size_t)r * N;
#pragma unroll
            for (int ci = 0; ci < 2; ci++) {
                int c = n0 + ci * 64 + tx * 4;
                if (c >= N) continue;
                float v[4];
#pragma unroll
                for (int j = 0; j < 4; j++) {
                    float x = acc[ri * 4 + i][ci * 4 + j];
                    if (EPI == 1) x = 1.f / (1.f + expf(-x));
                    v[j] = x;
                }
                *(float4*)(Crow + c) = make_float4(v[0], v[1], v[2], v[3]);
            }
        }
}

// ================================================================
// routing / dispatch / combine
// ================================================================
__global__ void routing_kernel(const float* __restrict__ scores,
                               const float* __restrict__ bias)
{
    int t = blockIdx.x * blockDim.x + threadIdx.x;
    if (t < E_) g_counts[t] = 0;   // fused zero_counts (completes before dispatch launch)
    if (t >= T_) return;
    float s[E_], m[E_];
    const float* sr = scores + t * E_;
#pragma unroll
    for (int e = 0; e < E_; e++) s[e] = sr[e];
    float gs[NGROUP];
    for (int gi = 0; gi < NGROUP; gi++) {
        float m1 = -1e30f, m2 = -1e30f;
        for (int j = 0; j < GSIZE; j++) {
            float v = s[gi * GSIZE + j] + bias[gi * GSIZE + j];
            if (v > m1) { m2 = m1; m1 = v; } else if (v > m2) m2 = v;
        }
        gs[gi] = m1 + m2;
    }
    bool gsel[NGROUP];
    for (int gi = 0; gi < NGROUP; gi++) gsel[gi] = false;
    for (int it = 0; it < TOPKG; it++) {
        float best = -1e30f; int bi = 0;
        for (int gi = 0; gi < NGROUP; gi++)
            if (!gsel[gi] && gs[gi] > best) { best = gs[gi]; bi = gi; }
        gsel[bi] = true;
    }
    for (int e = 0; e < E_; e++)
        m[e] = gsel[e / GSIZE] ? (s[e] + bias[e]) : 0.0f;
    float wsum = 0.f;
    int sel_e[TOPK]; float sel_w[TOPK];
    for (int k = 0; k < TOPK; k++) {
        float best = -1e30f; int bi = 0;
        for (int e = 0; e < E_; e++)
            if (m[e] > best) { best = m[e]; bi = e; }
        m[bi] = -1e30f;
        sel_e[k] = bi; sel_w[k] = s[bi]; wsum += s[bi];
    }
    float inv = RSCALE / (wsum + 1e-20f);
    for (int k = 0; k < TOPK; k++) {
        g_tidx[t * TOPK + k] = sel_e[k];
        g_tw[t * TOPK + k] = sel_w[k] * inv;
    }
}

__global__ void dispatch_kernel()
{
    int i = blockIdx.x * blockDim.x + threadIdx.x;
    if (i >= T_ * TOPK) return;
    int e = g_tidx[i];
    int p = atomicAdd(&g_counts[e], 1);
    if (p < CAP_) {
        int sl = e * CAP_ + p;
        g_toklist[sl] = i / TOPK;
        g_slot[i] = sl;
    } else g_slot[i] = -1;
}

__global__ void combine_kernel()
{
    const int nd4 = DL_ / 4;
    int idx = blockIdx.x * blockDim.x + threadIdx.x;
    if (idx >= T_ * nd4) return;
    int t = idx / nd4, d4 = idx % nd4;
    float4 acc = make_float4(0, 0, 0, 0);
#pragma unroll
    for (int k = 0; k < TOPK; k++) {
        int s = g_slot[t * TOPK + k];
        if (s >= 0) {
            float w = g_tw[t * TOPK + k];
            float4 v = *(const float4*)(g_eout + (size_t)s * DL_ + d4 * 4);
            acc.x += w * v.x; acc.y += w * v.y;
            acc.z += w * v.z; acc.w += w * v.w;
        }
    }
    *(float4*)(g_routed + (size_t)t * DL_ + d4 * 4) = acc;
}

// ================================================================
extern "C" void kernel_launch(void* const* d_in, const int* in_sizes, int n_in,
                              void* d_out, int out_size)
{
    (void)in_sizes; (void)n_in; (void)out_size;
    const float* x      = (const float*)d_in[0];
    const float* gate_w = (const float*)d_in[1];
    const float* gate_b = (const float*)d_in[2];
    const float* fc1_w  = (const float*)d_in[3];
    const float* fc2_w  = (const float*)d_in[4];
    const float* w1     = (const float*)d_in[5];
    const float* w2     = (const float*)d_in[6];
    const float* sw1    = (const float*)d_in[7];
    const float* sw2    = (const float*)d_in[8];
    float* out = (float*)d_out;

    float *scores, *xl, *s1, *h, *eout, *routed;
    int *toklist, *counts;
    cudaGetSymbolAddress((void**)&scores,  g_scores);
    cudaGetSymbolAddress((void**)&xl,      g_xl);
    cudaGetSymbolAddress((void**)&s1,      g_s1);
    cudaGetSymbolAddress((void**)&h,       g_h);
    cudaGetSymbolAddress((void**)&eout,    g_eout);
    cudaGetSymbolAddress((void**)&toklist, g_toklist);
    cudaGetSymbolAddress((void**)&routed,  g_routed);
    cudaGetSymbolAddress((void**)&counts,  g_counts);

    cudaFuncSetAttribute(hmma_gemm<0, false>, cudaFuncAttributeMaxDynamicSharedMemorySize, SMEM_BYTES);
    cudaFuncSetAttribute(hmma_gemm<2, false>, cudaFuncAttributeMaxDynamicSharedMemorySize, SMEM_BYTES);
    cudaFuncSetAttribute(hmma_gemm<0, true >, cudaFuncAttributeMaxDynamicSharedMemorySize, SMEM_BYTES);

    // 1) gate (SIMT, N=64): scores = sigmoid(x @ gate_w^T)        [launch 1]
    gemm_bt<1><<<dim3(1, T_ / 128, 1), 256>>>(x, gate_w, scores, T_, E_, D_);

    // 2) routing (+ fused counts zeroing)                          [launch 2]
    routing_kernel<<<T_ / 256, 256>>>(scores, gate_b);
    //    dispatch                                                  [launch 3]
    dispatch_kernel<<<(T_ * TOPK + 255) / 256, 256>>>();

    // 3) latent down-projection: xl = x @ fc1_w^T                  [launch 4 -> ncu target]
    hmma_gemm<0, false><<<dim3(DL_ / 128, T_ / 128, 1), 256, SMEM_BYTES>>>(
        x, fc1_w, xl, T_, DL_, D_, 0, 0, 0, nullptr, 0, nullptr);

    // 4) expert fc1: h[e] = relu2( gather(xl) @ w1[e]^T )
    hmma_gemm<2, false><<<dim3(I_ / 128, CAP_ / 128, E_), 256, SMEM_BYTES>>>(
        xl, w1, h, CAP_, I_, DL_,
        0, (long)I_ * DL_, (long)CAP_ * I_, toklist, CAP_, counts);

    // 5) expert fc2: eout[e] = h[e] @ w2[e]^T
    hmma_gemm<0, false><<<dim3(DL_ / 128, CAP_ / 128, E_), 256, SMEM_BYTES>>>(
        h, w2, eout, CAP_, DL_, I_,
        (long)CAP_ * I_, (long)DL_ * I_, (long)CAP_ * DL_, nullptr, 0, counts);

    // 6) combine
    combine_kernel<<<(T_ * (DL_ / 4) + 255) / 256, 256>>>();

    // 7) shared hidden: s1 = relu2(x @ sw1^T)
    hmma_gemm<2, false><<<dim3(SI_ / 128, T_ / 128, 1), 256, SMEM_BYTES>>>(
        x, sw1, s1, T_, SI_, D_, 0, 0, 0, nullptr, 0, nullptr);

    // 8) out = s1 @ sw2^T
    hmma_gemm<0, false><<<dim3(D_ / 128, T_ / 128, 1), 256, SMEM_BYTES>>>(
        s1, sw2, out, T_, D_, SI_, 0, 0, 0, nullptr, 0, nullptr);

    // 9) out += routed @ fc2_w^T
    hmma_gemm<0, true><<<dim3(D_ / 128, T_ / 128, 1), 256, SMEM_BYTES>>>(
        routed, fc2_w, out, T_, D_, DL_, 0, 0, 0, nullptr, 0, nullptr);
}